// round 7
// baseline (speedup 1.0000x reference)
#include <cuda_runtime.h>
#include <cuda_bf16.h>
#include <math.h>
#include <stdint.h>

// FlashChatglmAttention: B=4 S=1024 HID=4096 NH=32 HS=128 ROT=64
// R7: 64x64 warp tile (MMA:LDSM = 6.0, was 4.0) to unbind the smem crossbar.
// 256 threads, 8 warps 2x4, CTA tile 128x256, 3-stage cp.async ring.

#define TT    4096
#define HIDN  4096
#define NHEAD 32
#define HSZ   128
#define SEQ   1024
#define BATCH 4
#define GK    4096
#define LDP   8192      // packed row stride (hi|lo)

// ---------------- scratch (allocation-free) ----------------
__device__ float g_qkv [(size_t)TT * 3 * HIDN];
__device__ float g_q   [(size_t)TT * HIDN];
__device__ float g_attn[(size_t)TT * HIDN];
__device__ __nv_bfloat16 g_pa [(size_t)TT * LDP];
__device__ __nv_bfloat16 g_pbq[(size_t)3 * HIDN * LDP];
__device__ __nv_bfloat16 g_pbd[(size_t)HIDN * LDP];

// ---------------- PTX helpers (baseline ISA only) ----------------
__device__ __forceinline__ uint32_t smem_u32(const void* p) {
    uint32_t a;
    asm("{ .reg .u64 t; cvta.to.shared.u64 t, %1; cvt.u32.u64 %0, t; }" : "=r"(a) : "l"(p));
    return a;
}
__device__ __forceinline__ void cp_async16(uint32_t saddr, const void* gaddr) {
    asm volatile("cp.async.cg.shared.global [%0], [%1], 16;" :: "r"(saddr), "l"(gaddr));
}
__device__ __forceinline__ void cp_commit() { asm volatile("cp.async.commit_group;"); }
template<int N> __device__ __forceinline__ void cp_wait() {
    asm volatile("cp.async.wait_group %0;" :: "n"(N));
}
__device__ __forceinline__ void ldsm4(uint32_t* r, uint32_t addr) {
    asm volatile("ldmatrix.sync.aligned.m8n8.x4.shared.b16 {%0,%1,%2,%3}, [%4];"
                 : "=r"(r[0]), "=r"(r[1]), "=r"(r[2]), "=r"(r[3]) : "r"(addr));
}
__device__ __forceinline__ void mma16816(float* c, const uint32_t* a, const uint32_t* b) {
    asm volatile("mma.sync.aligned.m16n8k16.row.col.f32.bf16.bf16.f32 "
                 "{%0,%1,%2,%3}, {%4,%5,%6,%7}, {%8,%9}, {%0,%1,%2,%3};"
                 : "+f"(c[0]), "+f"(c[1]), "+f"(c[2]), "+f"(c[3])
                 : "r"(a[0]), "r"(a[1]), "r"(a[2]), "r"(a[3]), "r"(b[0]), "r"(b[1]));
}

// ---------------------------------------------------------------------------
// Pack kernels: fp32 -> bf16 hi | lo (residual).
// ---------------------------------------------------------------------------
__global__ __launch_bounds__(256) void pack_a(const float* __restrict__ X,
                                              __nv_bfloat16* __restrict__ Y) {
    const int idx = blockIdx.x * 256 + threadIdx.x;
    const int m = idx >> 12, k = idx & 4095;
    const float x = X[idx];
    const __nv_bfloat16 h = __float2bfloat16(x);
    const float r = x - __bfloat162float(h);
    Y[(size_t)m * LDP + k]      = h;
    Y[(size_t)m * LDP + GK + k] = __float2bfloat16(r);
}

// transpose pack: W[K][N] -> Y[N][hi(K)|lo(K)]
__global__ __launch_bounds__(1024) void pack_bt(const float* __restrict__ W,
                                                __nv_bfloat16* __restrict__ Y, int N) {
    __shared__ float sm[32][33];
    const int n0 = blockIdx.x << 5, k0 = blockIdx.y << 5;
    sm[threadIdx.y][threadIdx.x] = W[(size_t)(k0 + threadIdx.y) * N + n0 + threadIdx.x];
    __syncthreads();
    const float x = sm[threadIdx.x][threadIdx.y];       // W[k0+tx][n0+ty]
    const int n = n0 + threadIdx.y, k = k0 + threadIdx.x;
    const __nv_bfloat16 h = __float2bfloat16(x);
    const float r = x - __bfloat162float(h);
    Y[(size_t)n * LDP + k]      = h;
    Y[(size_t)n * LDP + GK + k] = __float2bfloat16(r);
}

// ---------------------------------------------------------------------------
// Fused-split bf16 mma.sync GEMM. 128x256 CTA tile, BK=32, 256 threads,
// 8 warps (2x4), 64x64 warp tile. Per k-tile smem: Ah|Al|Bh|Bl.
// 3-stage cp.async ring, one __syncthreads per k-tile.
// ---------------------------------------------------------------------------
#define ATILEB 10240u                  // A operand tile (128 rows * 80B)
#define BTILEB 20480u                  // B operand tile (256 rows * 80B)
#define STAGEB (2u * ATILEB + 2u * BTILEB)   // 61440
#define NSTAGE 3
#define GEMM_SMEM (NSTAGE * STAGEB)    // 184320 B

__global__ __launch_bounds__(256, 1) void tgemm(
    const __nv_bfloat16* __restrict__ A, const __nv_bfloat16* __restrict__ Bt,
    const float* __restrict__ bias, float* __restrict__ C, int M, int N)
{
    extern __shared__ __align__(16) char smraw[];
    const uint32_t sS = smem_u32(smraw);

    const int tid = threadIdx.x;
    const int wid = tid >> 5, lane = tid & 31;
    const int warp_m = wid >> 2, warp_n = wid & 3;

    const int m0 = blockIdx.y << 7, n0 = blockIdx.x << 8;
    const __nv_bfloat16* Ap = A + (size_t)m0 * LDP;
    const __nv_bfloat16* Bp = Bt + (size_t)n0 * LDP;

    // ldmatrix per-lane address components
    const int arow = lane & 15;                       // A: row within m16 tile
    const int akb  = (lane >> 4) * 16;                // A: k-byte offset
    const int brow = ((lane >> 4) << 3) + (lane & 7); // B: row within n16 tile
    const int bkb  = ((lane >> 3) & 1) * 16;          // B: k-byte offset

    float c[4][8][4];
    #pragma unroll
    for (int i = 0; i < 4; i++)
        #pragma unroll
        for (int j = 0; j < 8; j++)
            #pragma unroll
            for (int v = 0; v < 4; v++) c[i][j][v] = 0.f;

    const int NT = GK / 32;   // 128 k-tiles

    // loader: A 1024 chunks (hi|lo), B 2048 chunks (hi|lo); 12 chunks/thread
    auto issue = [&](int t) {
        const uint32_t sb = sS + (uint32_t)(t % NSTAGE) * STAGEB;
        const int ko = t * 32;
        #pragma unroll
        for (int j = 0; j < 4; j++) {               // A chunks (1024)
            const int id = tid + (j << 8);
            const int tile = id >> 9, w = id & 511;
            const int row = w >> 2, ch = w & 3;
            cp_async16(sb + tile * ATILEB + row * 80 + ch * 16,
                       Ap + (size_t)row * LDP + (tile ? GK : 0) + ko + ch * 8);
        }
        #pragma unroll
        for (int j = 0; j < 8; j++) {               // B chunks (2048)
            const int id = tid + (j << 8);
            const int tile = id >> 10, w = id & 1023;
            const int row = w >> 2, ch = w & 3;
            cp_async16(sb + 2 * ATILEB + tile * BTILEB + row * 80 + ch * 16,
                       Bp + (size_t)row * LDP + (tile ? GK : 0) + ko + ch * 8);
        }
        cp_commit();
    };

    issue(0); issue(1);
    for (int t = 0; t < NT; t++) {
        cp_wait<1>();
        __syncthreads();
        if (t + 2 < NT) issue(t + 2);
        const uint32_t bufo = sS + (uint32_t)(t % NSTAGE) * STAGEB;
        #pragma unroll
        for (int ks = 0; ks < 2; ks++) {
            uint32_t ah[4][4], al[4][4];
            #pragma unroll
            for (int mi = 0; mi < 4; mi++) {
                const uint32_t ra = bufo + (warp_m * 64 + mi * 16 + arow) * 80 + ks * 32 + akb;
                ldsm4(ah[mi], ra);
                ldsm4(al[mi], ra + ATILEB);
            }
            #pragma unroll
            for (int g = 0; g < 4; g++) {
                uint32_t bh[4], bl[4];
                const uint32_t rb = bufo + 2 * ATILEB
                                  + (warp_n * 64 + g * 16 + brow) * 80 + ks * 32 + bkb;
                ldsm4(bh, rb);
                ldsm4(bl, rb + BTILEB);
                #pragma unroll
                for (int mi = 0; mi < 4; mi++) {
                    mma16816(c[mi][g * 2 + 0], ah[mi], &bh[0]);
                    mma16816(c[mi][g * 2 + 1], ah[mi], &bh[2]);
                    mma16816(c[mi][g * 2 + 0], al[mi], &bh[0]);
                    mma16816(c[mi][g * 2 + 1], al[mi], &bh[2]);
                    mma16816(c[mi][g * 2 + 0], ah[mi], &bl[0]);
                    mma16816(c[mi][g * 2 + 1], ah[mi], &bl[2]);
                }
            }
        }
    }

    // epilogue
    const int gid = lane >> 2, tg = lane & 3;
    #pragma unroll
    for (int mi = 0; mi < 4; mi++) {
        const int row = m0 + warp_m * 64 + mi * 16 + gid;
        #pragma unroll
        for (int j = 0; j < 8; j++) {
            const int col = n0 + warp_n * 64 + j * 8 + tg * 2;
            float b0 = 0.f, b1 = 0.f;
            if (bias) { b0 = bias[col]; b1 = bias[col + 1]; }
            *(float2*)&C[(size_t)row * N + col] =
                make_float2(c[mi][j][0] + b0, c[mi][j][1] + b1);
            *(float2*)&C[(size_t)(row + 8) * N + col] =
                make_float2(c[mi][j][2] + b0, c[mi][j][3] + b1);
        }
    }
}

// ---------------------------------------------------------------------------
// Rotary (first 64 dims/head) + kv scatter. qkv: [t][12288] = q|k|v (NH,HS).
// ---------------------------------------------------------------------------
__global__ __launch_bounds__(256) void rotary_scatter(
    const float* __restrict__ qkv, const float* __restrict__ cosb,
    const float* __restrict__ sinb, const int* __restrict__ slots,
    float* __restrict__ qout, float* __restrict__ kout, float* __restrict__ vout)
{
    const int idx = blockIdx.x * 256 + threadIdx.x;
    const int t = idx >> 12;
    const int hd = idx & 4095;
    const int d = hd & 127;
    const float* base = qkv + (size_t)t * 12288;
    float qv = base[hd];
    float kv = base[4096 + hd];
    const float vv = base[8192 + hd];
    if (d < 64) {
        const int half = d & 31;
        const float c = cosb[(t << 5) + half];
        const float s = sinb[(t << 5) + half];
        if (d < 32) {
            qv = qv * c - base[hd + 32] * s;
            kv = kv * c - base[4096 + hd + 32] * s;
        } else {
            qv = qv * c + base[hd - 32] * s;
            kv = kv * c + base[4096 + hd - 32] * s;
        }
    }
    qout[idx] = qv;
    const size_t ko = ((size_t)slots[t] << 12) + hd;
    kout[ko] = kv;
    vout[ko] = vv;
}

// ---------------------------------------------------------------------------
// Causal flash attention, fp32. Br=Bc=64, 256 threads. grid (S/64, NH, B).
// ---------------------------------------------------------------------------
__global__ __launch_bounds__(256) void attn_kernel(
    const float* __restrict__ Q, const float* __restrict__ Kc,
    const float* __restrict__ Vc, float* __restrict__ O)
{
    extern __shared__ float smf[];
    float* Qs   = smf;
    float* Ks   = Qs + 64 * 128;
    float* Vs   = Ks + 64 * 129;
    float* Ps   = Vs + 64 * 132;
    float* mrow = Ps + 64 * 66;
    float* lrow = mrow + 64;
    float* arow = lrow + 64;

    const int qi = blockIdx.x, h = blockIdx.y, b = blockIdx.z;
    const int tid = threadIdx.x;
    const int tx = tid & 15, ty = tid >> 4;
    const int q0 = qi << 6;
    const float scale = 0.08838834764831845f;

    #pragma unroll
    for (int i = 0; i < 8; i++) {
        const int f = tid + (i << 8);
        const int r = f >> 5, dq = f & 31;
        const float4 v = *(const float4*)&Q[(size_t)(b * SEQ + q0 + r) * HIDN + h * HSZ + dq * 4];
        *(float4*)&Qs[r * 128 + dq * 4] =
            make_float4(v.x * scale, v.y * scale, v.z * scale, v.w * scale);
    }
    if (tid < 64) { mrow[tid] = -1e30f; lrow[tid] = 0.f; }
    float o[4][8];
    #pragma unroll
    for (int i = 0; i < 4; i++)
        #pragma unroll
        for (int j = 0; j < 8; j++) o[i][j] = 0.f;
    __syncthreads();

    for (int kt = 0; kt <= qi; kt++) {
        #pragma unroll
        for (int i = 0; i < 8; i++) {
            const int f = tid + (i << 8);
            const int r = f >> 5, dq = f & 31;
            const size_t g = (size_t)(b * SEQ + (kt << 6) + r) * HIDN + h * HSZ + dq * 4;
            const float4 kv = *(const float4*)&Kc[g];
            Ks[r * 129 + dq * 4 + 0] = kv.x; Ks[r * 129 + dq * 4 + 1] = kv.y;
            Ks[r * 129 + dq * 4 + 2] = kv.z; Ks[r * 129 + dq * 4 + 3] = kv.w;
            *(float4*)&Vs[r * 132 + dq * 4] = *(const float4*)&Vc[g];
        }
        __syncthreads();

        float s[4][4];
        #pragma unroll
        for (int i = 0; i < 4; i++)
            #pragma unroll
            for (int j = 0; j < 4; j++) s[i][j] = 0.f;
        #pragma unroll 4
        for (int d = 0; d < 128; d++) {
            float qr[4], kr[4];
            #pragma unroll
            for (int i = 0; i < 4; i++) qr[i] = Qs[(ty * 4 + i) * 128 + d];
            #pragma unroll
            for (int j = 0; j < 4; j++) kr[j] = Ks[(tx * 4 + j) * 129 + d];
            #pragma unroll
            for (int i = 0; i < 4; i++)
                #pragma unroll
                for (int j = 0; j < 4; j++)
                    s[i][j] = fmaf(qr[i], kr[j], s[i][j]);
        }
        #pragma unroll
        for (int i = 0; i < 4; i++) {
            const int qr_ = q0 + ty * 4 + i;
            #pragma unroll
            for (int j = 0; j < 4; j++) {
                const int kc = (kt << 6) + tx * 4 + j;
                Ps[(ty * 4 + i) * 66 + tx * 4 + j] = (kc <= qr_) ? s[i][j] : -1e30f;
            }
        }
        __syncthreads();

        if (tid < 64) {
            float mold = mrow[tid];
            float mnew = mold;
            float* pr = &Ps[tid * 66];
            #pragma unroll 8
            for (int cc = 0; cc < 64; cc++) mnew = fmaxf(mnew, pr[cc]);
            const float alpha = __expf(mold - mnew);
            float lsum = 0.f;
            #pragma unroll 8
            for (int cc = 0; cc < 64; cc++) {
                const float p = __expf(pr[cc] - mnew);
                pr[cc] = p; lsum += p;
            }
            lrow[tid] = lrow[tid] * alpha + lsum;
            mrow[tid] = mnew;
            arow[tid] = alpha;
        }
        __syncthreads();

        float al[4];
        #pragma unroll
        for (int i = 0; i < 4; i++) al[i] = arow[ty * 4 + i];
        #pragma unroll
        for (int i = 0; i < 4; i++)
            #pragma unroll
            for (int j = 0; j < 8; j++) o[i][j] *= al[i];
        #pragma unroll 2
        for (int k = 0; k < 64; k++) {
            float p[4];
            #pragma unroll
            for (int i = 0; i < 4; i++) p[i] = Ps[(ty * 4 + i) * 66 + k];
            const float4 v0 = *(const float4*)&Vs[k * 132 + tx * 8];
            const float4 v1 = *(const float4*)&Vs[k * 132 + tx * 8 + 4];
            const float vv[8] = {v0.x, v0.y, v0.z, v0.w, v1.x, v1.y, v1.z, v1.w};
            #pragma unroll
            for (int i = 0; i < 4; i++)
                #pragma unroll
                for (int j = 0; j < 8; j++)
                    o[i][j] = fmaf(p[i], vv[j], o[i][j]);
        }
        __syncthreads();
    }

    #pragma unroll
    for (int i = 0; i < 4; i++) {
        const float inv = 1.f / lrow[ty * 4 + i];
        float* dst = &O[(size_t)(b * SEQ + q0 + ty * 4 + i) * HIDN + h * HSZ + tx * 8];
        *(float4*)dst       = make_float4(o[i][0] * inv, o[i][1] * inv, o[i][2] * inv, o[i][3] * inv);
        *(float4*)(dst + 4) = make_float4(o[i][4] * inv, o[i][5] * inv, o[i][6] * inv, o[i][7] * inv);
    }
}

// ---------------------------------------------------------------------------
extern "C" void kernel_launch(void* const* d_in, const int* in_sizes, int n_in,
                              void* d_out, int out_size)
{
    (void)in_sizes; (void)n_in; (void)out_size;
    const float* hs     = (const float*)d_in[0];
    const float* cosb   = (const float*)d_in[1];
    const float* sinb   = (const float*)d_in[2];
    const float* wqkv   = (const float*)d_in[3];
    const float* bqkv   = (const float*)d_in[4];
    const float* wdense = (const float*)d_in[5];
    const int*   slots  = (const int*)d_in[8];

    float* out = (float*)d_out;
    float* kvk = out + (size_t)TT * HIDN;
    float* kvv = kvk + (size_t)TT * HIDN;

    float *qkv_p, *q_p, *attn_p;
    __nv_bfloat16 *pa, *pbq, *pbd;
    cudaGetSymbolAddress((void**)&qkv_p,  g_qkv);
    cudaGetSymbolAddress((void**)&q_p,    g_q);
    cudaGetSymbolAddress((void**)&attn_p, g_attn);
    cudaGetSymbolAddress((void**)&pa,     g_pa);
    cudaGetSymbolAddress((void**)&pbq,    g_pbq);
    cudaGetSymbolAddress((void**)&pbd,    g_pbd);

    cudaFuncSetAttribute(tgemm, cudaFuncAttributeMaxDynamicSharedMemorySize, GEMM_SMEM);

    // pack operands (hi/lo bf16 split)
    pack_a<<<(TT * GK) / 256, 256>>>(hs, pa);
    pack_bt<<<dim3(3 * HIDN / 32, GK / 32), dim3(32, 32)>>>(wqkv, pbq, 3 * HIDN);
    pack_bt<<<dim3(HIDN / 32, GK / 32), dim3(32, 32)>>>(wdense, pbd, HIDN);

    // 1. QKV projection on tensor cores (+bias)
    tgemm<<<dim3(3 * HIDN / 256, TT / 128), 256, GEMM_SMEM>>>(pa, pbq, bqkv, qkv_p, TT, 3 * HIDN);

    // 2. rotary + kv-cache scatter
    rotary_scatter<<<(TT * HIDN) / 256, 256>>>(qkv_p, cosb, sinb, slots, q_p, kvk, kvv);

    // 3. causal flash attention (fp32 SIMT)
    const size_t asmem = (size_t)(64 * 128 + 64 * 129 + 64 * 132 + 64 * 66 + 192) * sizeof(float);
    cudaFuncSetAttribute(attn_kernel, cudaFuncAttributeMaxDynamicSharedMemorySize, (int)asmem);
    attn_kernel<<<dim3(SEQ / 64, NHEAD, BATCH), 256, asmem>>>(q_p, kvk, kvv, attn_p);

    // 4. dense projection on tensor cores
    pack_a<<<(TT * GK) / 256, 256>>>(attn_p, pa);
    tgemm<<<dim3(HIDN / 256, TT / 128), 256, GEMM_SMEM>>>(pa, pbd, nullptr, out, TT, HIDN);
}

// round 9
// speedup vs baseline: 1.0774x; 1.0774x over previous
#include <cuda_runtime.h>
#include <cuda_bf16.h>
#include <math.h>
#include <stdint.h>

// FlashChatglmAttention: B=4 S=1024 HID=4096 NH=32 HS=128 ROT=64
// R8: R5 tile config (128x128, 8 warps, 32x64 warp tile) with a 2-stage
// cp.async ring (80KB smem) so 2 CTAs fit per SM — their barrier/wait
// bubbles interleave and keep the tensor pipe fed.

#define TT    4096
#define HIDN  4096
#define NHEAD 32
#define HSZ   128
#define SEQ   1024
#define BATCH 4
#define GK    4096
#define LDP   8192      // packed row stride (hi|lo)

// ---------------- scratch (allocation-free) ----------------
__device__ float g_qkv [(size_t)TT * 3 * HIDN];
__device__ float g_q   [(size_t)TT * HIDN];
__device__ float g_attn[(size_t)TT * HIDN];
__device__ __nv_bfloat16 g_pa [(size_t)TT * LDP];
__device__ __nv_bfloat16 g_pbq[(size_t)3 * HIDN * LDP];
__device__ __nv_bfloat16 g_pbd[(size_t)HIDN * LDP];

// ---------------- PTX helpers (baseline ISA only) ----------------
__device__ __forceinline__ uint32_t smem_u32(const void* p) {
    uint32_t a;
    asm("{ .reg .u64 t; cvta.to.shared.u64 t, %1; cvt.u32.u64 %0, t; }" : "=r"(a) : "l"(p));
    return a;
}
__device__ __forceinline__ void cp_async16(uint32_t saddr, const void* gaddr) {
    asm volatile("cp.async.cg.shared.global [%0], [%1], 16;" :: "r"(saddr), "l"(gaddr));
}
__device__ __forceinline__ void cp_commit() { asm volatile("cp.async.commit_group;"); }
template<int N> __device__ __forceinline__ void cp_wait() {
    asm volatile("cp.async.wait_group %0;" :: "n"(N));
}
__device__ __forceinline__ void ldsm4(uint32_t* r, uint32_t addr) {
    asm volatile("ldmatrix.sync.aligned.m8n8.x4.shared.b16 {%0,%1,%2,%3}, [%4];"
                 : "=r"(r[0]), "=r"(r[1]), "=r"(r[2]), "=r"(r[3]) : "r"(addr));
}
__device__ __forceinline__ void mma16816(float* c, const uint32_t* a, const uint32_t* b) {
    asm volatile("mma.sync.aligned.m16n8k16.row.col.f32.bf16.bf16.f32 "
                 "{%0,%1,%2,%3}, {%4,%5,%6,%7}, {%8,%9}, {%0,%1,%2,%3};"
                 : "+f"(c[0]), "+f"(c[1]), "+f"(c[2]), "+f"(c[3])
                 : "r"(a[0]), "r"(a[1]), "r"(a[2]), "r"(a[3]), "r"(b[0]), "r"(b[1]));
}

// ---------------------------------------------------------------------------
// Pack kernels: fp32 -> bf16 hi | lo (residual).
// ---------------------------------------------------------------------------
__global__ __launch_bounds__(256) void pack_a(const float* __restrict__ X,
                                              __nv_bfloat16* __restrict__ Y) {
    const int idx = blockIdx.x * 256 + threadIdx.x;
    const int m = idx >> 12, k = idx & 4095;
    const float x = X[idx];
    const __nv_bfloat16 h = __float2bfloat16(x);
    const float r = x - __bfloat162float(h);
    Y[(size_t)m * LDP + k]      = h;
    Y[(size_t)m * LDP + GK + k] = __float2bfloat16(r);
}

// transpose pack: W[K][N] -> Y[N][hi(K)|lo(K)]
__global__ __launch_bounds__(1024) void pack_bt(const float* __restrict__ W,
                                                __nv_bfloat16* __restrict__ Y, int N) {
    __shared__ float sm[32][33];
    const int n0 = blockIdx.x << 5, k0 = blockIdx.y << 5;
    sm[threadIdx.y][threadIdx.x] = W[(size_t)(k0 + threadIdx.y) * N + n0 + threadIdx.x];
    __syncthreads();
    const float x = sm[threadIdx.x][threadIdx.y];       // W[k0+tx][n0+ty]
    const int n = n0 + threadIdx.y, k = k0 + threadIdx.x;
    const __nv_bfloat16 h = __float2bfloat16(x);
    const float r = x - __bfloat162float(h);
    Y[(size_t)n * LDP + k]      = h;
    Y[(size_t)n * LDP + GK + k] = __float2bfloat16(r);
}

// ---------------------------------------------------------------------------
// Fused-split bf16 mma.sync GEMM. 128x128 CTA tile, BK=32, 256 threads,
// 8 warps (4x2), 32x64 warp tile. Per k-tile smem: Ah|Al|Bh|Bl.
// 2-stage cp.async ring (80KB) -> 2 CTAs/SM interleave barrier bubbles.
// ---------------------------------------------------------------------------
#define TILEB 10240u               // bytes per operand tile (128 rows * 80B)
#define STAGEB (4u * TILEB)        // Ah|Al|Bh|Bl
#define NSTAGE 2
#define GEMM_SMEM (NSTAGE * STAGEB)   // 81920 B

__global__ __launch_bounds__(256, 2) void tgemm(
    const __nv_bfloat16* __restrict__ A, const __nv_bfloat16* __restrict__ Bt,
    const float* __restrict__ bias, float* __restrict__ C, int M, int N)
{
    extern __shared__ __align__(16) char smraw[];
    const uint32_t sS = smem_u32(smraw);

    const int tid = threadIdx.x;
    const int wid = tid >> 5, lane = tid & 31;
    const int warp_m = wid >> 1, warp_n = wid & 1;

    const int m0 = blockIdx.y << 7, n0 = blockIdx.x << 7;
    const __nv_bfloat16* Ap = A + (size_t)m0 * LDP;
    const __nv_bfloat16* Bp = Bt + (size_t)n0 * LDP;

    // ldmatrix per-lane address components
    const int arow = lane & 15;                       // A: row within m16 tile
    const int akb  = (lane >> 4) * 16;                // A: k-byte offset
    const int brow = ((lane >> 4) << 3) + (lane & 7); // B: row within n16 tile
    const int bkb  = ((lane >> 3) & 1) * 16;          // B: k-byte offset

    float c[2][8][4];
    #pragma unroll
    for (int i = 0; i < 2; i++)
        #pragma unroll
        for (int j = 0; j < 8; j++)
            #pragma unroll
            for (int v = 0; v < 4; v++) c[i][j][v] = 0.f;

    const int NT = GK / 32;   // 128 k-tiles

    // loader: each thread moves 2 x 16B chunks per operand tile
    const int lrow0 = tid >> 2, lch = tid & 3;
    const uint32_t so0 = (uint32_t)(lrow0 * 80 + lch * 16);
    const uint32_t so1 = (uint32_t)((lrow0 + 64) * 80 + lch * 16);
    const __nv_bfloat16* Ag0 = Ap + (size_t)lrow0 * LDP + lch * 8;
    const __nv_bfloat16* Ag1 = Ap + (size_t)(lrow0 + 64) * LDP + lch * 8;
    const __nv_bfloat16* Bg0 = Bp + (size_t)lrow0 * LDP + lch * 8;
    const __nv_bfloat16* Bg1 = Bp + (size_t)(lrow0 + 64) * LDP + lch * 8;

    auto issue = [&](int t) {
        const uint32_t sb = sS + (uint32_t)(t & 1) * STAGEB;
        const int ko = t * 32;
        cp_async16(sb + so0,                 Ag0 + ko);
        cp_async16(sb + so1,                 Ag1 + ko);
        cp_async16(sb + TILEB + so0,         Ag0 + GK + ko);
        cp_async16(sb + TILEB + so1,         Ag1 + GK + ko);
        cp_async16(sb + 2 * TILEB + so0,     Bg0 + ko);
        cp_async16(sb + 2 * TILEB + so1,     Bg1 + ko);
        cp_async16(sb + 3 * TILEB + so0,     Bg0 + GK + ko);
        cp_async16(sb + 3 * TILEB + so1,     Bg1 + GK + ko);
        cp_commit();
    };

    issue(0);
    for (int t = 0; t < NT; t++) {
        cp_wait<0>();
        __syncthreads();
        // safe: sync above guarantees all warps finished iter t-1, whose
        // compute read buffer (t+1)&1 — now being overwritten by issue(t+1).
        if (t + 1 < NT) issue(t + 1);
        const uint32_t bufo = sS + (uint32_t)(t & 1) * STAGEB;
        #pragma unroll
        for (int ks = 0; ks < 2; ks++) {
            uint32_t ah[2][4], al[2][4], bh[4][4], bl[4][4];
            #pragma unroll
            for (int i = 0; i < 2; i++) {
                const uint32_t ra = bufo + (warp_m * 32 + i * 16 + arow) * 80 + ks * 32 + akb;
                ldsm4(ah[i], ra);
                ldsm4(al[i], ra + TILEB);
            }
            #pragma unroll
            for (int g = 0; g < 4; g++) {
                const uint32_t rb = bufo + 2 * TILEB + (warp_n * 64 + g * 16 + brow) * 80 + ks * 32 + bkb;
                ldsm4(bh[g], rb);
                ldsm4(bl[g], rb + TILEB);
            }
            #pragma unroll
            for (int i = 0; i < 2; i++)
                #pragma unroll
                for (int g = 0; g < 4; g++) {
                    mma16816(c[i][g * 2 + 0], ah[i], &bh[g][0]);
                    mma16816(c[i][g * 2 + 1], ah[i], &bh[g][2]);
                    mma16816(c[i][g * 2 + 0], al[i], &bh[g][0]);
                    mma16816(c[i][g * 2 + 1], al[i], &bh[g][2]);
                    mma16816(c[i][g * 2 + 0], ah[i], &bl[g][0]);
                    mma16816(c[i][g * 2 + 1], ah[i], &bl[g][2]);
                }
        }
    }

    // epilogue
    const int gid = lane >> 2, tg = lane & 3;
    #pragma unroll
    for (int i = 0; i < 2; i++) {
        const int row = m0 + warp_m * 32 + i * 16 + gid;
        #pragma unroll
        for (int j = 0; j < 8; j++) {
            const int col = n0 + warp_n * 64 + j * 8 + tg * 2;
            float b0 = 0.f, b1 = 0.f;
            if (bias) { b0 = bias[col]; b1 = bias[col + 1]; }
            *(float2*)&C[(size_t)row * N + col] =
                make_float2(c[i][j][0] + b0, c[i][j][1] + b1);
            *(float2*)&C[(size_t)(row + 8) * N + col] =
                make_float2(c[i][j][2] + b0, c[i][j][3] + b1);
        }
    }
}

// ---------------------------------------------------------------------------
// Rotary (first 64 dims/head) + kv scatter. qkv: [t][12288] = q|k|v (NH,HS).
// ---------------------------------------------------------------------------
__global__ __launch_bounds__(256) void rotary_scatter(
    const float* __restrict__ qkv, const float* __restrict__ cosb,
    const float* __restrict__ sinb, const int* __restrict__ slots,
    float* __restrict__ qout, float* __restrict__ kout, float* __restrict__ vout)
{
    const int idx = blockIdx.x * 256 + threadIdx.x;
    const int t = idx >> 12;
    const int hd = idx & 4095;
    const int d = hd & 127;
    const float* base = qkv + (size_t)t * 12288;
    float qv = base[hd];
    float kv = base[4096 + hd];
    const float vv = base[8192 + hd];
    if (d < 64) {
        const int half = d & 31;
        const float c = cosb[(t << 5) + half];
        const float s = sinb[(t << 5) + half];
        if (d < 32) {
            qv = qv * c - base[hd + 32] * s;
            kv = kv * c - base[4096 + hd + 32] * s;
        } else {
            qv = qv * c + base[hd - 32] * s;
            kv = kv * c + base[4096 + hd - 32] * s;
        }
    }
    qout[idx] = qv;
    const size_t ko = ((size_t)slots[t] << 12) + hd;
    kout[ko] = kv;
    vout[ko] = vv;
}

// ---------------------------------------------------------------------------
// Causal flash attention, fp32. Br=Bc=64, 256 threads. grid (S/64, NH, B).
// ---------------------------------------------------------------------------
__global__ __launch_bounds__(256) void attn_kernel(
    const float* __restrict__ Q, const float* __restrict__ Kc,
    const float* __restrict__ Vc, float* __restrict__ O)
{
    extern __shared__ float smf[];
    float* Qs   = smf;
    float* Ks   = Qs + 64 * 128;
    float* Vs   = Ks + 64 * 129;
    float* Ps   = Vs + 64 * 132;
    float* mrow = Ps + 64 * 66;
    float* lrow = mrow + 64;
    float* arow = lrow + 64;

    const int qi = blockIdx.x, h = blockIdx.y, b = blockIdx.z;
    const int tid = threadIdx.x;
    const int tx = tid & 15, ty = tid >> 4;
    const int q0 = qi << 6;
    const float scale = 0.08838834764831845f;

    #pragma unroll
    for (int i = 0; i < 8; i++) {
        const int f = tid + (i << 8);
        const int r = f >> 5, dq = f & 31;
        const float4 v = *(const float4*)&Q[(size_t)(b * SEQ + q0 + r) * HIDN + h * HSZ + dq * 4];
        *(float4*)&Qs[r * 128 + dq * 4] =
            make_float4(v.x * scale, v.y * scale, v.z * scale, v.w * scale);
    }
    if (tid < 64) { mrow[tid] = -1e30f; lrow[tid] = 0.f; }
    float o[4][8];
    #pragma unroll
    for (int i = 0; i < 4; i++)
        #pragma unroll
        for (int j = 0; j < 8; j++) o[i][j] = 0.f;
    __syncthreads();

    for (int kt = 0; kt <= qi; kt++) {
        #pragma unroll
        for (int i = 0; i < 8; i++) {
            const int f = tid + (i << 8);
            const int r = f >> 5, dq = f & 31;
            const size_t g = (size_t)(b * SEQ + (kt << 6) + r) * HIDN + h * HSZ + dq * 4;
            const float4 kv = *(const float4*)&Kc[g];
            Ks[r * 129 + dq * 4 + 0] = kv.x; Ks[r * 129 + dq * 4 + 1] = kv.y;
            Ks[r * 129 + dq * 4 + 2] = kv.z; Ks[r * 129 + dq * 4 + 3] = kv.w;
            *(float4*)&Vs[r * 132 + dq * 4] = *(const float4*)&Vc[g];
        }
        __syncthreads();

        float s[4][4];
        #pragma unroll
        for (int i = 0; i < 4; i++)
            #pragma unroll
            for (int j = 0; j < 4; j++) s[i][j] = 0.f;
        #pragma unroll 4
        for (int d = 0; d < 128; d++) {
            float qr[4], kr[4];
            #pragma unroll
            for (int i = 0; i < 4; i++) qr[i] = Qs[(ty * 4 + i) * 128 + d];
            #pragma unroll
            for (int j = 0; j < 4; j++) kr[j] = Ks[(tx * 4 + j) * 129 + d];
            #pragma unroll
            for (int i = 0; i < 4; i++)
                #pragma unroll
                for (int j = 0; j < 4; j++)
                    s[i][j] = fmaf(qr[i], kr[j], s[i][j]);
        }
        #pragma unroll
        for (int i = 0; i < 4; i++) {
            const int qr_ = q0 + ty * 4 + i;
            #pragma unroll
            for (int j = 0; j < 4; j++) {
                const int kc = (kt << 6) + tx * 4 + j;
                Ps[(ty * 4 + i) * 66 + tx * 4 + j] = (kc <= qr_) ? s[i][j] : -1e30f;
            }
        }
        __syncthreads();

        if (tid < 64) {
            float mold = mrow[tid];
            float mnew = mold;
            float* pr = &Ps[tid * 66];
            #pragma unroll 8
            for (int cc = 0; cc < 64; cc++) mnew = fmaxf(mnew, pr[cc]);
            const float alpha = __expf(mold - mnew);
            float lsum = 0.f;
            #pragma unroll 8
            for (int cc = 0; cc < 64; cc++) {
                const float p = __expf(pr[cc] - mnew);
                pr[cc] = p; lsum += p;
            }
            lrow[tid] = lrow[tid] * alpha + lsum;
            mrow[tid] = mnew;
            arow[tid] = alpha;
        }
        __syncthreads();

        float al[4];
        #pragma unroll
        for (int i = 0; i < 4; i++) al[i] = arow[ty * 4 + i];
        #pragma unroll
        for (int i = 0; i < 4; i++)
            #pragma unroll
            for (int j = 0; j < 8; j++) o[i][j] *= al[i];
        #pragma unroll 2
        for (int k = 0; k < 64; k++) {
            float p[4];
            #pragma unroll
            for (int i = 0; i < 4; i++) p[i] = Ps[(ty * 4 + i) * 66 + k];
            const float4 v0 = *(const float4*)&Vs[k * 132 + tx * 8];
            const float4 v1 = *(const float4*)&Vs[k * 132 + tx * 8 + 4];
            const float vv[8] = {v0.x, v0.y, v0.z, v0.w, v1.x, v1.y, v1.z, v1.w};
            #pragma unroll
            for (int i = 0; i < 4; i++)
                #pragma unroll
                for (int j = 0; j < 8; j++)
                    o[i][j] = fmaf(p[i], vv[j], o[i][j]);
        }
        __syncthreads();
    }

    #pragma unroll
    for (int i = 0; i < 4; i++) {
        const float inv = 1.f / lrow[ty * 4 + i];
        float* dst = &O[(size_t)(b * SEQ + q0 + ty * 4 + i) * HIDN + h * HSZ + tx * 8];
        *(float4*)dst       = make_float4(o[i][0] * inv, o[i][1] * inv, o[i][2] * inv, o[i][3] * inv);
        *(float4*)(dst + 4) = make_float4(o[i][4] * inv, o[i][5] * inv, o[i][6] * inv, o[i][7] * inv);
    }
}

// ---------------------------------------------------------------------------
extern "C" void kernel_launch(void* const* d_in, const int* in_sizes, int n_in,
                              void* d_out, int out_size)
{
    (void)in_sizes; (void)n_in; (void)out_size;
    const float* hs     = (const float*)d_in[0];
    const float* cosb   = (const float*)d_in[1];
    const float* sinb   = (const float*)d_in[2];
    const float* wqkv   = (const float*)d_in[3];
    const float* bqkv   = (const float*)d_in[4];
    const float* wdense = (const float*)d_in[5];
    const int*   slots  = (const int*)d_in[8];

    float* out = (float*)d_out;
    float* kvk = out + (size_t)TT * HIDN;
    float* kvv = kvk + (size_t)TT * HIDN;

    float *qkv_p, *q_p, *attn_p;
    __nv_bfloat16 *pa, *pbq, *pbd;
    cudaGetSymbolAddress((void**)&qkv_p,  g_qkv);
    cudaGetSymbolAddress((void**)&q_p,    g_q);
    cudaGetSymbolAddress((void**)&attn_p, g_attn);
    cudaGetSymbolAddress((void**)&pa,     g_pa);
    cudaGetSymbolAddress((void**)&pbq,    g_pbq);
    cudaGetSymbolAddress((void**)&pbd,    g_pbd);

    cudaFuncSetAttribute(tgemm, cudaFuncAttributeMaxDynamicSharedMemorySize, GEMM_SMEM);

    // pack operands (hi/lo bf16 split)
    pack_a<<<(TT * GK) / 256, 256>>>(hs, pa);
    pack_bt<<<dim3(3 * HIDN / 32, GK / 32), dim3(32, 32)>>>(wqkv, pbq, 3 * HIDN);
    pack_bt<<<dim3(HIDN / 32, GK / 32), dim3(32, 32)>>>(wdense, pbd, HIDN);

    // 1. QKV projection on tensor cores (+bias)
    tgemm<<<dim3(3 * HIDN / 128, TT / 128), 256, GEMM_SMEM>>>(pa, pbq, bqkv, qkv_p, TT, 3 * HIDN);

    // 2. rotary + kv-cache scatter
    rotary_scatter<<<(TT * HIDN) / 256, 256>>>(qkv_p, cosb, sinb, slots, q_p, kvk, kvv);

    // 3. causal flash attention (fp32 SIMT)
    const size_t asmem = (size_t)(64 * 128 + 64 * 129 + 64 * 132 + 64 * 66 + 192) * sizeof(float);
    cudaFuncSetAttribute(attn_kernel, cudaFuncAttributeMaxDynamicSharedMemorySize, (int)asmem);
    attn_kernel<<<dim3(SEQ / 64, NHEAD, BATCH), 256, asmem>>>(q_p, kvk, kvv, attn_p);

    // 4. dense projection on tensor cores
    pack_a<<<(TT * GK) / 256, 256>>>(attn_p, pa);
    tgemm<<<dim3(HIDN / 128, TT / 128), 256, GEMM_SMEM>>>(pa, pbd, nullptr, out, TT, HIDN);
}

// round 13
// speedup vs baseline: 1.3122x; 1.2179x over previous
#include <cuda_runtime.h>
#include <cuda_bf16.h>
#include <math.h>
#include <stdint.h>

// FlashChatglmAttention: B=4 S=1024 HID=4096 NH=32 HS=128 ROT=64
// R12: R11 with the buffer-size bug fixed: g_qhl/g_khl are [bh][s][hi|lo]
// = TT*8192 elements (NOT TT*256 — that OOB stomped every later buffer).
// GEMMs as R8; attention full hi/lo split mma.sync; fp32 softmax.

#define TT    4096
#define HIDN  4096
#define NHEAD 32
#define HSZ   128
#define SEQ   1024
#define BATCH 4
#define GK    4096
#define LDP   8192      // packed row stride (hi|lo)

// ---------------- scratch (allocation-free) ----------------
__device__ float g_qkv [(size_t)TT * 3 * HIDN];
__device__ __nv_bfloat16 g_pa [(size_t)TT * LDP];
__device__ __nv_bfloat16 g_pbq[(size_t)3 * HIDN * LDP];
__device__ __nv_bfloat16 g_pbd[(size_t)HIDN * LDP];
__device__ __nv_bfloat16 g_qhl[(size_t)TT * 8192];  // [bh][s][hi(128)|lo(128)] scaled
__device__ __nv_bfloat16 g_khl[(size_t)TT * 8192];  // [bh][s][hi|lo]
__device__ __nv_bfloat16 g_vth[(size_t)TT * HIDN];  // [bh][d][s] hi
__device__ __nv_bfloat16 g_vtl[(size_t)TT * HIDN];  // [bh][d][s] lo

// ---------------- PTX helpers (baseline ISA only) ----------------
__device__ __forceinline__ uint32_t smem_u32(const void* p) {
    uint32_t a;
    asm("{ .reg .u64 t; cvta.to.shared.u64 t, %1; cvt.u32.u64 %0, t; }" : "=r"(a) : "l"(p));
    return a;
}
__device__ __forceinline__ void cp_async16(uint32_t saddr, const void* gaddr) {
    asm volatile("cp.async.cg.shared.global [%0], [%1], 16;" :: "r"(saddr), "l"(gaddr));
}
__device__ __forceinline__ void cp_commit() { asm volatile("cp.async.commit_group;"); }
template<int N> __device__ __forceinline__ void cp_wait() {
    asm volatile("cp.async.wait_group %0;" :: "n"(N));
}
__device__ __forceinline__ void ldsm4(uint32_t* r, uint32_t addr) {
    asm volatile("ldmatrix.sync.aligned.m8n8.x4.shared.b16 {%0,%1,%2,%3}, [%4];"
                 : "=r"(r[0]), "=r"(r[1]), "=r"(r[2]), "=r"(r[3]) : "r"(addr));
}
__device__ __forceinline__ void mma16816(float* c, const uint32_t* a, const uint32_t* b) {
    asm volatile("mma.sync.aligned.m16n8k16.row.col.f32.bf16.bf16.f32 "
                 "{%0,%1,%2,%3}, {%4,%5,%6,%7}, {%8,%9}, {%0,%1,%2,%3};"
                 : "+f"(c[0]), "+f"(c[1]), "+f"(c[2]), "+f"(c[3])
                 : "r"(a[0]), "r"(a[1]), "r"(a[2]), "r"(a[3]), "r"(b[0]), "r"(b[1]));
}
__device__ __forceinline__ uint32_t packbf(float lo, float hi) {
    uint32_t r;
    asm("cvt.rn.bf16x2.f32 %0, %1, %2;" : "=r"(r) : "f"(hi), "f"(lo));
    return r;
}

// ---------------------------------------------------------------------------
// Pack kernels: fp32 -> bf16 hi | lo (residual).
// ---------------------------------------------------------------------------
__global__ __launch_bounds__(256) void pack_a(const float* __restrict__ X,
                                              __nv_bfloat16* __restrict__ Y) {
    const int idx = blockIdx.x * 256 + threadIdx.x;
    const int m = idx >> 12, k = idx & 4095;
    const float x = X[idx];
    const __nv_bfloat16 h = __float2bfloat16(x);
    const float r = x - __bfloat162float(h);
    Y[(size_t)m * LDP + k]      = h;
    Y[(size_t)m * LDP + GK + k] = __float2bfloat16(r);
}

__global__ __launch_bounds__(1024) void pack_bt(const float* __restrict__ W,
                                                __nv_bfloat16* __restrict__ Y, int N) {
    __shared__ float sm[32][33];
    const int n0 = blockIdx.x << 5, k0 = blockIdx.y << 5;
    sm[threadIdx.y][threadIdx.x] = W[(size_t)(k0 + threadIdx.y) * N + n0 + threadIdx.x];
    __syncthreads();
    const float x = sm[threadIdx.x][threadIdx.y];
    const int n = n0 + threadIdx.y, k = k0 + threadIdx.x;
    const __nv_bfloat16 h = __float2bfloat16(x);
    const float r = x - __bfloat162float(h);
    Y[(size_t)n * LDP + k]      = h;
    Y[(size_t)n * LDP + GK + k] = __float2bfloat16(r);
}

// ---------------------------------------------------------------------------
// Fused-split bf16 mma.sync GEMM (identical to R8 best).
// ---------------------------------------------------------------------------
#define TILEB 10240u
#define STAGEB (4u * TILEB)
#define NSTAGE 2
#define GEMM_SMEM (NSTAGE * STAGEB)   // 81920 B

__global__ __launch_bounds__(256, 2) void tgemm(
    const __nv_bfloat16* __restrict__ A, const __nv_bfloat16* __restrict__ Bt,
    const float* __restrict__ bias, float* __restrict__ C, int M, int N)
{
    extern __shared__ __align__(16) char smraw[];
    const uint32_t sS = smem_u32(smraw);

    const int tid = threadIdx.x;
    const int wid = tid >> 5, lane = tid & 31;
    const int warp_m = wid >> 1, warp_n = wid & 1;

    const int m0 = blockIdx.y << 7, n0 = blockIdx.x << 7;
    const __nv_bfloat16* Ap = A + (size_t)m0 * LDP;
    const __nv_bfloat16* Bp = Bt + (size_t)n0 * LDP;

    const int arow = lane & 15;
    const int akb  = (lane >> 4) * 16;
    const int brow = ((lane >> 4) << 3) + (lane & 7);
    const int bkb  = ((lane >> 3) & 1) * 16;

    float c[2][8][4];
    #pragma unroll
    for (int i = 0; i < 2; i++)
        #pragma unroll
        for (int j = 0; j < 8; j++)
            #pragma unroll
            for (int v = 0; v < 4; v++) c[i][j][v] = 0.f;

    const int NT = GK / 32;

    const int lrow0 = tid >> 2, lch = tid & 3;
    const uint32_t so0 = (uint32_t)(lrow0 * 80 + lch * 16);
    const uint32_t so1 = (uint32_t)((lrow0 + 64) * 80 + lch * 16);
    const __nv_bfloat16* Ag0 = Ap + (size_t)lrow0 * LDP + lch * 8;
    const __nv_bfloat16* Ag1 = Ap + (size_t)(lrow0 + 64) * LDP + lch * 8;
    const __nv_bfloat16* Bg0 = Bp + (size_t)lrow0 * LDP + lch * 8;
    const __nv_bfloat16* Bg1 = Bp + (size_t)(lrow0 + 64) * LDP + lch * 8;

    auto issue = [&](int t) {
        const uint32_t sb = sS + (uint32_t)(t & 1) * STAGEB;
        const int ko = t * 32;
        cp_async16(sb + so0,             Ag0 + ko);
        cp_async16(sb + so1,             Ag1 + ko);
        cp_async16(sb + TILEB + so0,     Ag0 + GK + ko);
        cp_async16(sb + TILEB + so1,     Ag1 + GK + ko);
        cp_async16(sb + 2 * TILEB + so0, Bg0 + ko);
        cp_async16(sb + 2 * TILEB + so1, Bg1 + ko);
        cp_async16(sb + 3 * TILEB + so0, Bg0 + GK + ko);
        cp_async16(sb + 3 * TILEB + so1, Bg1 + GK + ko);
        cp_commit();
    };

    issue(0);
    for (int t = 0; t < NT; t++) {
        cp_wait<0>();
        __syncthreads();
        if (t + 1 < NT) issue(t + 1);
        const uint32_t bufo = sS + (uint32_t)(t & 1) * STAGEB;
        #pragma unroll
        for (int ks = 0; ks < 2; ks++) {
            uint32_t ah[2][4], al[2][4], bh[4][4], bl[4][4];
            #pragma unroll
            for (int i = 0; i < 2; i++) {
                const uint32_t ra = bufo + (warp_m * 32 + i * 16 + arow) * 80 + ks * 32 + akb;
                ldsm4(ah[i], ra);
                ldsm4(al[i], ra + TILEB);
            }
            #pragma unroll
            for (int g = 0; g < 4; g++) {
                const uint32_t rb = bufo + 2 * TILEB + (warp_n * 64 + g * 16 + brow) * 80 + ks * 32 + bkb;
                ldsm4(bh[g], rb);
                ldsm4(bl[g], rb + TILEB);
            }
            #pragma unroll
            for (int i = 0; i < 2; i++)
                #pragma unroll
                for (int g = 0; g < 4; g++) {
                    mma16816(c[i][g * 2 + 0], ah[i], &bh[g][0]);
                    mma16816(c[i][g * 2 + 1], ah[i], &bh[g][2]);
                    mma16816(c[i][g * 2 + 0], al[i], &bh[g][0]);
                    mma16816(c[i][g * 2 + 1], al[i], &bh[g][2]);
                    mma16816(c[i][g * 2 + 0], ah[i], &bl[g][0]);
                    mma16816(c[i][g * 2 + 1], ah[i], &bl[g][2]);
                }
        }
    }

    const int gid = lane >> 2, tg = lane & 3;
    #pragma unroll
    for (int i = 0; i < 2; i++) {
        const int row = m0 + warp_m * 32 + i * 16 + gid;
        #pragma unroll
        for (int j = 0; j < 8; j++) {
            const int col = n0 + warp_n * 64 + j * 8 + tg * 2;
            float b0 = 0.f, b1 = 0.f;
            if (bias) { b0 = bias[col]; b1 = bias[col + 1]; }
            *(float2*)&C[(size_t)row * N + col] =
                make_float2(c[i][j][0] + b0, c[i][j][1] + b1);
            *(float2*)&C[(size_t)(row + 8) * N + col] =
                make_float2(c[i][j][2] + b0, c[i][j][3] + b1);
        }
    }
}

// ---------------------------------------------------------------------------
// Rotary + kv scatter + hi/lo bf16 Q,K emission ([bh][s][hi|lo]).
// ---------------------------------------------------------------------------
__global__ __launch_bounds__(256) void rotary_scatter(
    const float* __restrict__ qkv, const float* __restrict__ cosb,
    const float* __restrict__ sinb, const int* __restrict__ slots,
    float* __restrict__ kout, float* __restrict__ vout,
    __nv_bfloat16* __restrict__ qhl, __nv_bfloat16* __restrict__ khl)
{
    const int idx = blockIdx.x * 256 + threadIdx.x;
    const int t = idx >> 12;
    const int hd = idx & 4095;
    const int d = hd & 127;
    const int h = hd >> 7;
    const float* base = qkv + (size_t)t * 12288;
    float qv = base[hd];
    float kv = base[4096 + hd];
    const float vv = base[8192 + hd];
    if (d < 64) {
        const int half = d & 31;
        const float c = cosb[(t << 5) + half];
        const float s = sinb[(t << 5) + half];
        if (d < 32) {
            qv = qv * c - base[hd + 32] * s;
            kv = kv * c - base[4096 + hd + 32] * s;
        } else {
            qv = qv * c + base[hd - 32] * s;
            kv = kv * c + base[4096 + hd - 32] * s;
        }
    }
    const size_t ko = ((size_t)slots[t] << 12) + hd;
    kout[ko] = kv;
    vout[ko] = vv;
    // [bh][s][hi|lo]
    const int b = t >> 10, s = t & 1023;
    const size_t bi = (((size_t)(b * NHEAD + h)) * SEQ + s) * 256 + d;
    const float qs = qv * 0.08838834764831845f;
    const __nv_bfloat16 qh = __float2bfloat16(qs);
    const __nv_bfloat16 kh = __float2bfloat16(kv);
    qhl[bi]       = qh;
    qhl[bi + 128] = __float2bfloat16(qs - __bfloat162float(qh));
    khl[bi]       = kh;
    khl[bi + 128] = __float2bfloat16(kv - __bfloat162float(kh));
}

// kvv fp32 [t][h*128+d] -> vth/vtl bf16 [bh][d][s]
__global__ __launch_bounds__(1024) void transp_vhl(const float* __restrict__ vsrc,
                                                   __nv_bfloat16* __restrict__ vth,
                                                   __nv_bfloat16* __restrict__ vtl)
{
    __shared__ float sm[32][33];
    const int d0 = blockIdx.x << 5, s0 = blockIdx.y << 5;
    const int bh = blockIdx.z;
    const int b = bh >> 5, h = bh & 31;
    sm[threadIdx.y][threadIdx.x] =
        vsrc[((size_t)(b * SEQ + s0 + threadIdx.y)) * HIDN + h * HSZ + d0 + threadIdx.x];
    __syncthreads();
    const float x = sm[threadIdx.x][threadIdx.y];   // v[s0+tx][d0+ty]
    const __nv_bfloat16 hi = __float2bfloat16(x);
    const size_t o = ((size_t)bh * HSZ + d0 + threadIdx.y) * SEQ + s0 + threadIdx.x;
    vth[o] = hi;
    vtl[o] = __float2bfloat16(x - __bfloat162float(hi));
}

// ---------------------------------------------------------------------------
// Tensor-core causal flash attention, full hi/lo split. Br=128 (8 warps,
// m16 each), Bc=64. Q/K [bh][s][hi|lo] (512B rows), V [bh][d][s] hi+lo.
// fp32 softmax. Output written as hi/lo packed A rows into g_pa.
// ---------------------------------------------------------------------------
#define QK_STRIDE 528u                      // 512B data + 16B pad
#define VS_STRIDE 144u                      // 128B data + 16B pad
#define AQ_BYTES  (128u * QK_STRIDE)        // 67584
#define AK_BYTES  (64u * QK_STRIDE)         // 33792
#define AV_BYTES  (128u * VS_STRIDE)        // 18432
#define ASTAGE    (AK_BYTES + 2u * AV_BYTES)    // 70656
#define ATTN_SMEM (AQ_BYTES + 2u * ASTAGE)      // 208896

__global__ __launch_bounds__(256, 1) void attn_mma(
    const __nv_bfloat16* __restrict__ qhl, const __nv_bfloat16* __restrict__ khl,
    const __nv_bfloat16* __restrict__ vth, const __nv_bfloat16* __restrict__ vtl,
    __nv_bfloat16* __restrict__ Y)
{
    extern __shared__ __align__(16) char smraw[];
    const uint32_t sQ = smem_u32(smraw);

    const int qi = blockIdx.x, h = blockIdx.y, b = blockIdx.z;
    const int tid = threadIdx.x;
    const int warp = tid >> 5, lane = tid & 31;
    const int gid = lane >> 2, tg = lane & 3;
    const int q0 = qi << 7;

    const size_t bh = (size_t)(b * NHEAD + h);
    const __nv_bfloat16* Qg = qhl + (bh * SEQ + q0) * 256;
    const __nv_bfloat16* Kg = khl + bh * SEQ * 256;
    const __nv_bfloat16* Vhg = vth + bh * HSZ * SEQ;
    const __nv_bfloat16* Vlg = vtl + bh * HSZ * SEQ;

    const int arow = lane & 15;
    const int akb  = (lane >> 4) * 16;
    const int brow = ((lane >> 4) << 3) + (lane & 7);
    const int bkb  = ((lane >> 3) & 1) * 16;

    auto issueK = [&](int kt, int buf) {
        const uint32_t sb = sQ + AQ_BYTES + (uint32_t)buf * ASTAGE;
        const __nv_bfloat16* kg = Kg + (size_t)(kt << 6) * 256;
        const int so = kt << 6;
        #pragma unroll
        for (int j = 0; j < 8; j++) {           // K: 64 rows x 32 chunks
            const int c = tid + (j << 8);
            const int row = c >> 5, ch = c & 31;
            cp_async16(sb + row * QK_STRIDE + ch * 16, kg + (size_t)row * 256 + ch * 8);
        }
        #pragma unroll
        for (int j = 0; j < 4; j++) {           // V hi: 128 rows x 8 chunks
            const int c = tid + (j << 8);
            const int row = c >> 3, ch = c & 7;
            cp_async16(sb + AK_BYTES + row * VS_STRIDE + ch * 16,
                       Vhg + (size_t)row * SEQ + so + ch * 8);
        }
        #pragma unroll
        for (int j = 0; j < 4; j++) {           // V lo
            const int c = tid + (j << 8);
            const int row = c >> 3, ch = c & 7;
            cp_async16(sb + AK_BYTES + AV_BYTES + row * VS_STRIDE + ch * 16,
                       Vlg + (size_t)row * SEQ + so + ch * 8);
        }
        cp_commit();
    };

    // prologue: Q tile (128 rows x 32 chunks) + first K/V stage
    #pragma unroll
    for (int j = 0; j < 16; j++) {
        const int c = tid + (j << 8);
        const int row = c >> 5, ch = c & 31;
        cp_async16(sQ + row * QK_STRIDE + ch * 16, Qg + (size_t)row * 256 + ch * 8);
    }
    cp_commit();
    issueK(0, 0);
    cp_wait<0>();
    __syncthreads();

    // Q fragments: m16 rows per warp, 8 k16 tiles, hi + lo
    uint32_t qfh[8][4], qfl[8][4];
    #pragma unroll
    for (int kd = 0; kd < 8; kd++) {
        const uint32_t ra = sQ + (warp * 16 + arow) * QK_STRIDE + kd * 32 + akb;
        ldsm4(qfh[kd], ra);
        ldsm4(qfl[kd], ra + 256);
    }

    float o[16][4];
    #pragma unroll
    for (int g = 0; g < 16; g++)
        #pragma unroll
        for (int v = 0; v < 4; v++) o[g][v] = 0.f;
    float m0 = -1e30f, m1 = -1e30f, l0 = 0.f, l1 = 0.f;

    const int NKT = 2 * qi + 2;
    for (int kt = 0; kt < NKT; kt++) {
        cp_wait<0>();
        __syncthreads();
        if (kt + 1 < NKT) issueK(kt + 1, (kt + 1) & 1);
        const uint32_t sb = sQ + AQ_BYTES + (uint32_t)(kt & 1) * ASTAGE;

        // S = Q K^T with 3 split combos
        float s[8][4];
        #pragma unroll
        for (int g = 0; g < 8; g++)
            #pragma unroll
            for (int v = 0; v < 4; v++) s[g][v] = 0.f;
        #pragma unroll
        for (int kd = 0; kd < 8; kd++) {
            #pragma unroll
            for (int g4 = 0; g4 < 4; g4++) {
                uint32_t kfh[4], kfl[4];
                const uint32_t rb = sb + (g4 * 16 + brow) * QK_STRIDE + kd * 32 + bkb;
                ldsm4(kfh, rb);
                ldsm4(kfl, rb + 256);
                mma16816(s[g4 * 2 + 0], qfh[kd], &kfh[0]);
                mma16816(s[g4 * 2 + 1], qfh[kd], &kfh[2]);
                mma16816(s[g4 * 2 + 0], qfl[kd], &kfh[0]);
                mma16816(s[g4 * 2 + 1], qfl[kd], &kfh[2]);
                mma16816(s[g4 * 2 + 0], qfh[kd], &kfl[0]);
                mma16816(s[g4 * 2 + 1], qfh[kd], &kfl[2]);
            }
        }

        // causal mask on diagonal-crossing tiles
        if (kt >= 2 * qi) {
            const int r0 = q0 + warp * 16 + gid, r1 = r0 + 8;
            const int c0 = kt << 6;
            #pragma unroll
            for (int g = 0; g < 8; g++) {
                const int col = c0 + g * 8 + tg * 2;
                if (col     > r0) s[g][0] = -1e30f;
                if (col + 1 > r0) s[g][1] = -1e30f;
                if (col     > r1) s[g][2] = -1e30f;
                if (col + 1 > r1) s[g][3] = -1e30f;
            }
        }

        // online softmax
        float mt0 = -1e30f, mt1 = -1e30f;
        #pragma unroll
        for (int g = 0; g < 8; g++) {
            mt0 = fmaxf(mt0, fmaxf(s[g][0], s[g][1]));
            mt1 = fmaxf(mt1, fmaxf(s[g][2], s[g][3]));
        }
        mt0 = fmaxf(mt0, __shfl_xor_sync(0xffffffffu, mt0, 1));
        mt0 = fmaxf(mt0, __shfl_xor_sync(0xffffffffu, mt0, 2));
        mt1 = fmaxf(mt1, __shfl_xor_sync(0xffffffffu, mt1, 1));
        mt1 = fmaxf(mt1, __shfl_xor_sync(0xffffffffu, mt1, 2));
        const float mn0 = fmaxf(m0, mt0), mn1 = fmaxf(m1, mt1);
        const float a0 = __expf(m0 - mn0), a1 = __expf(m1 - mn1);
        float ls0 = 0.f, ls1 = 0.f;
        #pragma unroll
        for (int g = 0; g < 8; g++) {
            s[g][0] = __expf(s[g][0] - mn0); ls0 += s[g][0];
            s[g][1] = __expf(s[g][1] - mn0); ls0 += s[g][1];
            s[g][2] = __expf(s[g][2] - mn1); ls1 += s[g][2];
            s[g][3] = __expf(s[g][3] - mn1); ls1 += s[g][3];
        }
        ls0 += __shfl_xor_sync(0xffffffffu, ls0, 1);
        ls0 += __shfl_xor_sync(0xffffffffu, ls0, 2);
        ls1 += __shfl_xor_sync(0xffffffffu, ls1, 1);
        ls1 += __shfl_xor_sync(0xffffffffu, ls1, 2);
        l0 = l0 * a0 + ls0; l1 = l1 * a1 + ls1;
        m0 = mn0; m1 = mn1;
        #pragma unroll
        for (int g = 0; g < 16; g++) {
            o[g][0] *= a0; o[g][1] *= a0;
            o[g][2] *= a1; o[g][3] *= a1;
        }

        // P hi/lo fragments (accumulator -> A fragment identity)
        uint32_t pah[4][4], pal[4][4];
        #pragma unroll
        for (int kp = 0; kp < 4; kp++) {
            const float s00 = s[2 * kp][0],     s01 = s[2 * kp][1];
            const float s02 = s[2 * kp][2],     s03 = s[2 * kp][3];
            const float s10 = s[2 * kp + 1][0], s11 = s[2 * kp + 1][1];
            const float s12 = s[2 * kp + 1][2], s13 = s[2 * kp + 1][3];
            pah[kp][0] = packbf(s00, s01);
            pah[kp][1] = packbf(s02, s03);
            pah[kp][2] = packbf(s10, s11);
            pah[kp][3] = packbf(s12, s13);
            const float h00 = __bfloat162float(*(const __nv_bfloat16*)&pah[kp][0]);
            const float h01 = __bfloat162float(*((const __nv_bfloat16*)&pah[kp][0] + 1));
            const float h02 = __bfloat162float(*(const __nv_bfloat16*)&pah[kp][1]);
            const float h03 = __bfloat162float(*((const __nv_bfloat16*)&pah[kp][1] + 1));
            const float h10 = __bfloat162float(*(const __nv_bfloat16*)&pah[kp][2]);
            const float h11 = __bfloat162float(*((const __nv_bfloat16*)&pah[kp][2] + 1));
            const float h12 = __bfloat162float(*(const __nv_bfloat16*)&pah[kp][3]);
            const float h13 = __bfloat162float(*((const __nv_bfloat16*)&pah[kp][3] + 1));
            pal[kp][0] = packbf(s00 - h00, s01 - h01);
            pal[kp][1] = packbf(s02 - h02, s03 - h03);
            pal[kp][2] = packbf(s10 - h10, s11 - h11);
            pal[kp][3] = packbf(s12 - h12, s13 - h13);
        }

        // O += P V with 3 split combos
        #pragma unroll
        for (int kp = 0; kp < 4; kp++) {
            #pragma unroll
            for (int g4 = 0; g4 < 8; g4++) {
                uint32_t vfh[4], vfl[4];
                const uint32_t rb = sb + AK_BYTES + (g4 * 16 + brow) * VS_STRIDE + kp * 32 + bkb;
                ldsm4(vfh, rb);
                ldsm4(vfl, rb + AV_BYTES);
                mma16816(o[g4 * 2 + 0], pah[kp], &vfh[0]);
                mma16816(o[g4 * 2 + 1], pah[kp], &vfh[2]);
                mma16816(o[g4 * 2 + 0], pal[kp], &vfh[0]);
                mma16816(o[g4 * 2 + 1], pal[kp], &vfh[2]);
                mma16816(o[g4 * 2 + 0], pah[kp], &vfl[0]);
                mma16816(o[g4 * 2 + 1], pah[kp], &vfl[2]);
            }
        }
    }

    // epilogue: normalize, hi/lo split, write packed A rows
    const float i0 = 1.f / l0, i1 = 1.f / l1;
    const size_t t0 = (size_t)(b * SEQ + q0 + warp * 16 + gid);
    #pragma unroll
    for (int g = 0; g < 16; g++) {
        const int k = h * HSZ + g * 8 + tg * 2;
        {
            const float v0 = o[g][0] * i0, v1 = o[g][1] * i0;
            const __nv_bfloat16 h0 = __float2bfloat16(v0), h1 = __float2bfloat16(v1);
            __nv_bfloat16* yp = Y + t0 * LDP + k;
            *(uint32_t*)yp = ((uint32_t)*(const unsigned short*)&h1 << 16) |
                             (uint32_t)*(const unsigned short*)&h0;
            const __nv_bfloat16 r0b = __float2bfloat16(v0 - __bfloat162float(h0));
            const __nv_bfloat16 r1b = __float2bfloat16(v1 - __bfloat162float(h1));
            *(uint32_t*)(yp + GK) = ((uint32_t)*(const unsigned short*)&r1b << 16) |
                                    (uint32_t)*(const unsigned short*)&r0b;
        }
        {
            const float v0 = o[g][2] * i1, v1 = o[g][3] * i1;
            const __nv_bfloat16 h0 = __float2bfloat16(v0), h1 = __float2bfloat16(v1);
            __nv_bfloat16* yp = Y + (t0 + 8) * LDP + k;
            *(uint32_t*)yp = ((uint32_t)*(const unsigned short*)&h1 << 16) |
                             (uint32_t)*(const unsigned short*)&h0;
            const __nv_bfloat16 r0b = __float2bfloat16(v0 - __bfloat162float(h0));
            const __nv_bfloat16 r1b = __float2bfloat16(v1 - __bfloat162float(h1));
            *(uint32_t*)(yp + GK) = ((uint32_t)*(const unsigned short*)&r1b << 16) |
                                    (uint32_t)*(const unsigned short*)&r0b;
        }
    }
}

// ---------------------------------------------------------------------------
extern "C" void kernel_launch(void* const* d_in, const int* in_sizes, int n_in,
                              void* d_out, int out_size)
{
    (void)in_sizes; (void)n_in; (void)out_size;
    const float* hs     = (const float*)d_in[0];
    const float* cosb   = (const float*)d_in[1];
    const float* sinb   = (const float*)d_in[2];
    const float* wqkv   = (const float*)d_in[3];
    const float* bqkv   = (const float*)d_in[4];
    const float* wdense = (const float*)d_in[5];
    const int*   slots  = (const int*)d_in[8];

    float* out = (float*)d_out;
    float* kvk = out + (size_t)TT * HIDN;
    float* kvv = kvk + (size_t)TT * HIDN;

    float* qkv_p;
    __nv_bfloat16 *pa, *pbq, *pbd, *qhl, *khl, *vth, *vtl;
    cudaGetSymbolAddress((void**)&qkv_p, g_qkv);
    cudaGetSymbolAddress((void**)&pa,    g_pa);
    cudaGetSymbolAddress((void**)&pbq,   g_pbq);
    cudaGetSymbolAddress((void**)&pbd,   g_pbd);
    cudaGetSymbolAddress((void**)&qhl,   g_qhl);
    cudaGetSymbolAddress((void**)&khl,   g_khl);
    cudaGetSymbolAddress((void**)&vth,   g_vth);
    cudaGetSymbolAddress((void**)&vtl,   g_vtl);

    cudaFuncSetAttribute(tgemm, cudaFuncAttributeMaxDynamicSharedMemorySize, GEMM_SMEM);
    cudaFuncSetAttribute(attn_mma, cudaFuncAttributeMaxDynamicSharedMemorySize, ATTN_SMEM);

    // pack operands (hi/lo bf16 split)
    pack_a<<<(TT * GK) / 256, 256>>>(hs, pa);
    pack_bt<<<dim3(3 * HIDN / 32, GK / 32), dim3(32, 32)>>>(wqkv, pbq, 3 * HIDN);
    pack_bt<<<dim3(HIDN / 32, GK / 32), dim3(32, 32)>>>(wdense, pbd, HIDN);

    // 1. QKV projection (+bias)
    tgemm<<<dim3(3 * HIDN / 128, TT / 128), 256, GEMM_SMEM>>>(pa, pbq, bqkv, qkv_p, TT, 3 * HIDN);

    // 2. rotary + kv scatter + hi/lo Q,K emission; V transpose+split from kvv
    rotary_scatter<<<(TT * HIDN) / 256, 256>>>(qkv_p, cosb, sinb, slots,
                                               kvk, kvv, qhl, khl);
    transp_vhl<<<dim3(HSZ / 32, SEQ / 32, BATCH * NHEAD), dim3(32, 32)>>>(kvv, vth, vtl);

    // 3. tensor-core flash attention (writes packed A for the dense GEMM)
    attn_mma<<<dim3(SEQ / 128, NHEAD, BATCH), 256, ATTN_SMEM>>>(qhl, khl, vth, vtl, pa);

    // 4. dense projection
    tgemm<<<dim3(HIDN / 128, TT / 128), 256, GEMM_SMEM>>>(pa, pbd, nullptr, out, TT, HIDN);
}